// round 14
// baseline (speedup 1.0000x reference)
#include <cuda_runtime.h>
#include <math.h>
#include <stdint.h>

#define TT 512
#define NN 256
#define CC 256
#define SS 48
#define LL 97
#define LOG2E 1.4426950408889634f
#define LN2   0.6931471805599453f

#define ROWS 2                      // batch rows per CTA
#define CHUNK 16                    // timesteps per ring buffer
#define NBUF 4
#define NCHUNK (TT / CHUNK)         // 32
#define GRID (NN / ROWS)            // 128
#define SLOTS 64                    // floats per (t,row) tile
#define GW 8                        // gather warps (wid 0..7)
#define CW 2                        // compute warps (wid 8..9) - hi-wid priority
#define NWARPS (GW + CW)
#define NTHREADS (NWARPS * 32)      // 320
#define TILE_F (ROWS * SLOTS)       // 128 floats per timestep
#define BUF_F (CHUNK * TILE_F)      // 2048 floats per buffer
#define RING_F (NBUF * BUF_F)       // 8192 floats = 32 KB
#define NPAR 3                      // scratch triple-buffer (prefetch distance 2)
#define SCRATCH_F (NPAR * GW * 1024)  // 3 x 8 warps x 1024 floats = 96 KB
#define SMEM_BYTES ((RING_F + SCRATCH_F) * 4)   // 131072

__device__ float g_loss_n[NN];
__device__ int   g_count;           // zero-init; self-resetting per launch

__device__ __forceinline__ uint32_t s2u(const void* p) {
    return (uint32_t)__cvta_generic_to_shared(p);
}
__device__ __forceinline__ float ex2f(float x) {
    float y; asm("ex2.approx.ftz.f32 %0, %1;" : "=f"(y) : "f"(x)); return y;
}
__device__ __forceinline__ float lg2f(float x) {
    float y; asm("lg2.approx.ftz.f32 %0, %1;" : "=f"(y) : "f"(x)); return y;
}
__device__ __forceinline__ void mbar_wait(uint32_t addr, uint32_t parity) {
    asm volatile(
        "{\n"
        ".reg .pred P;\n"
        "WL%=:\n"
        "mbarrier.try_wait.parity.acquire.cta.shared::cta.b64 P, [%0], %1, 0x989680;\n"
        "@P bra WD%=;\n"
        "bra WL%=;\n"
        "WD%=:\n"
        "}\n" :: "r"(addr), "r"(parity) : "memory");
}

#define CP16(dst_u32, src_ptr) \
    asm volatile("cp.async.cg.shared.global [%0], [%1], 16;" :: "r"(dst_u32), "l"(src_ptr) : "memory")
#define CP_COMMIT() asm volatile("cp.async.commit_group;" ::: "memory")
#define CP_WAIT2()  asm volatile("cp.async.wait_group 2;" ::: "memory")
#define CP_WAIT1()  asm volatile("cp.async.wait_group 1;" ::: "memory")
#define CP_WAIT0()  asm volatile("cp.async.wait_group 0;" ::: "memory")

struct AState { float a0, a1, a2, a3, xs; int X; };

__device__ __forceinline__ void alpha_step(AState& s, float pb, float pa, float pc,
                                           float sk1f, float sk3f)
{
    float p3 = __shfl_up_sync(0xffffffffu, s.a3, 1);
    float q3 = p3 * s.xs;                  // neighbor a3 rescaled (0 on lane 0)
    float t01 = s.a0 + s.a1;
    float t23 = s.a2 + s.a3;
    float n0v = (s.a0 + q3) * pb;
    float n1v = fmaf(sk1f, q3, t01) * pa;
    float n2v = (s.a1 + s.a2) * pb;
    float n3v = fmaf(sk3f, s.a1, t23) * pc;
    s.a0 = n0v; s.a1 = n1v; s.a2 = n2v; s.a3 = n3v;
}

// PROVEN two-shfl renorm with empty-lane frame adoption. The adoption is
// LOAD-BEARING: rows with repeated labels advance the wavefront slower than
// 2 states/step, so lanes can stay empty arbitrarily long (round-13 lesson).
__device__ __forceinline__ void renorm(AState& s, int lane)
{
    float mx = fmaxf(fmaxf(s.a0, s.a1), fmaxf(s.a2, s.a3));
    int Xp = __shfl_up_sync(0xffffffffu, s.X, 1);      // neighbor X (pre-update)
    int e  = (int)(__float_as_uint(mx) >> 23);
    int eu = (e > 0) ? e : 127;
    int Xn = s.X + (eu - 127);
    Xn = (mx == 0.0f && lane > 0) ? Xp : Xn;           // empty lanes adopt neighbor frame
    float scale = __uint_as_float((unsigned)(254 - eu) << 23);
    s.a0 *= scale; s.a1 *= scale; s.a2 *= scale; s.a3 *= scale;
    s.X = Xn;
    int Xp2 = __shfl_up_sync(0xffffffffu, s.X, 1);     // neighbor FINAL X
    int d = min(126, max(-126, Xp2 - s.X));
    float x = __uint_as_float((unsigned)(d + 127) << 23);
    s.xs = (lane == 0) ? 0.0f : x;
}

__global__ __launch_bounds__(NTHREADS, 1)
void ctc_fused(const float* __restrict__ logits,
               const int*   __restrict__ labels,
               const int*   __restrict__ pred_sizes,
               const int*   __restrict__ tgt_sizes,
               float*       __restrict__ out)
{
    extern __shared__ __align__(128) float smem[];
    float* ring    = smem;                 // RING_F floats
    float* scratch = smem + RING_F;        // SCRATCH_F floats (NPAR x GW x 1024)
    __shared__ __align__(8) unsigned long long mb_full[NBUF];
    __shared__ __align__(8) unsigned long long mb_empty[NBUF];
    __shared__ float red[NWARPS];
    __shared__ int s_last;

    const int tid  = threadIdx.x;
    const int wid  = tid >> 5;
    const int lane = tid & 31;
    const int n0   = blockIdx.x * ROWS;

    if (tid == 0) {
        #pragma unroll
        for (int b = 0; b < NBUF; b++) {
            asm volatile("mbarrier.init.shared.b64 [%0], %1;" :: "r"(s2u(&mb_full[b])),  "r"(GW));
            asm volatile("mbarrier.init.shared.b64 [%0], %1;" :: "r"(s2u(&mb_empty[b])), "r"(CW));
        }
    }
    __syncthreads();

    if (wid < GW) {
        // ===== gather warps: cp.async triple-buffered, prefetch distance 2 =====
        const uint32_t scr_u32 = s2u(scratch) + (uint32_t)wid * 4096u;   // + parity*32768
        float* scr_gen = scratch + wid * 1024;                           // + parity*8192

        int ch00 = 0, ch01 = 0, ch10 = 0, ch11 = 0;
        if (lane < 24) {
            int2 l0 = *(const int2*)(labels + n0 * SS + 2 * lane);
            int2 l1 = *(const int2*)(labels + (n0 + 1) * SS + 2 * lane);
            ch00 = l0.x; ch01 = l0.y; ch10 = l1.x; ch11 = l1.y;
        }

        #define GISSUE(k) do {                                                            \
            const uint32_t dst = scr_u32 + (uint32_t)(((k) % NPAR) * 32768);              \
            const float* sa = logits + ((size_t)((k) * CHUNK + wid)     * NN + n0) * CC;  \
            const float* sb = logits + ((size_t)((k) * CHUNK + wid + 8) * NN + n0) * CC;  \
            _Pragma("unroll")                                                             \
            for (int i = 0; i < 4; i++) {                                                 \
                CP16(dst + (lane + 32 * i) * 16u,         sa + (lane + 32 * i) * 4);      \
                CP16(dst + 2048u + (lane + 32 * i) * 16u, sb + (lane + 32 * i) * 4);      \
            }                                                                             \
            CP_COMMIT();                                                                  \
        } while (0)

        GISSUE(0);
        GISSUE(1);

        #pragma unroll 1
        for (int c = 0; c < NCHUNK; c++) {
            const int b = c % NBUF;
            if (c + 2 < NCHUNK) { GISSUE(c + 2); CP_WAIT2(); }
            else if (c + 1 < NCHUNK) { CP_WAIT1(); }
            else { CP_WAIT0(); }
            __syncwarp();

            if (c >= NBUF) mbar_wait(s2u(&mb_empty[b]), ((c / NBUF) - 1) & 1);

            // gather 49 channels per row -> linear probs -> ring
            const float* buf = scr_gen + (c % NPAR) * 8192;
            if (lane <= 24) {
                #pragma unroll
                for (int s = 0; s < 2; s++) {
                    const float* base = buf + s * 512;
                    const int j = wid + s * 8;
                    float p00 = ex2f(base[ch00]       * LOG2E);
                    float p01 = ex2f(base[ch01]       * LOG2E);
                    float p10 = ex2f(base[256 + ch10] * LOG2E);
                    float p11 = ex2f(base[256 + ch11] * LOG2E);
                    float* tp = ring + (size_t)(b * CHUNK + j) * TILE_F;
                    *(float2*)(tp + 2 * lane)         = make_float2(p00, p01);
                    *(float2*)(tp + SLOTS + 2 * lane) = make_float2(p10, p11);
                }
            }
            __syncwarp();
            if (lane == 0)
                asm volatile("mbarrier.arrive.shared.b64 _, [%0];" :: "r"(s2u(&mb_full[b])) : "memory");
        }
        #undef GISSUE
    } else {
        // ================= compute warps (one batch row each) =================
        const int row = wid - GW;
        const int n = n0 + row;
        int lab_a = (2 * lane     < SS) ? labels[n * SS + 2 * lane]     : 0;
        int lab_b = (2 * lane + 1 < SS) ? labels[n * SS + 2 * lane + 1] : 0;
        int lab_p = (2 * lane - 1 >= 0) ? labels[n * SS + 2 * lane - 1] : 0;
        const float sk1f = ((lab_a != 0) && (lab_a != lab_p)) ? 1.0f : 0.0f;
        const float sk3f = ((lab_b != 0) && (lab_b != lab_a)) ? 1.0f : 0.0f;
        const int in_len = pred_sizes[n];
        const int pair_off = (lane < 24) ? 2 * lane : 48;

        AState s;
        s.a0 = 0.0f; s.a1 = 0.0f; s.a2 = 0.0f; s.a3 = 0.0f;
        s.X = 0;
        s.xs = (lane == 0) ? 0.0f : 1.0f;

        #pragma unroll 1
        for (int c = 0; c < NCHUNK; c++) {
            const int b = c % NBUF;
            mbar_wait(s2u(&mb_full[b]), (c / NBUF) & 1);
            const float* base = ring + (size_t)(b * CHUNK) * TILE_F + row * SLOTS;
            const bool fast = (c > 0) && ((c + 1) * CHUNK <= in_len);

            if (fast) {
                // batch-load the entire chunk to registers, then free the ring slot early
                float pa[CHUNK], pc[CHUNK], pb[CHUNK];
                #pragma unroll
                for (int j = 0; j < CHUNK; j++) {
                    const float* rp = base + j * TILE_F;
                    float2 f2 = *(const float2*)(rp + pair_off);
                    pa[j] = f2.x; pc[j] = f2.y;
                    pb[j] = rp[48];
                }
                __syncwarp();
                if (lane == 0)
                    asm volatile("mbarrier.arrive.shared.b64 _, [%0];" :: "r"(s2u(&mb_empty[b])) : "memory");

                #pragma unroll
                for (int j = 0; j < CHUNK; j++) {
                    alpha_step(s, pb[j], pa[j], pc[j], sk1f, sk3f);
                    if ((j & 3) == 3) renorm(s, lane);
                }
            } else {
                #pragma unroll 1
                for (int j = 0; j < CHUNK; j++) {
                    const int t = c * CHUNK + j;
                    const float* rp = base + j * TILE_F;
                    if (t < in_len) {
                        float2 f2 = *(const float2*)(rp + pair_off);
                        float pbv = rp[48];
                        if (t == 0) {
                            if (lane == 0) { s.a0 = pbv; s.a1 = f2.x; }
                        } else {
                            alpha_step(s, pbv, f2.x, f2.y, sk1f, sk3f);
                        }
                        if ((t & 3) == 3) renorm(s, lane);
                    }
                }
                if (lane == 0)
                    asm volatile("mbarrier.arrive.shared.b64 _, [%0];" :: "r"(s2u(&mb_empty[b])) : "memory");
            }
        }

        // per-row loss: true log2(alpha_l) = lg2(stored) + X_lane
        {
            int tl = tgt_sizes[n];
            int i1 = 2 * tl - 1, i2 = 2 * tl;
            int sel1 = i1 & 3, sl1 = i1 >> 2;
            float x1 = (sel1 == 0) ? s.a0 : (sel1 == 1) ? s.a1 : (sel1 == 2) ? s.a2 : s.a3;
            x1 = __shfl_sync(0xffffffffu, x1, sl1);
            float X1 = (float)__shfl_sync(0xffffffffu, s.X, sl1);
            int sel2 = i2 & 3, sl2 = i2 >> 2;
            float x2 = (sel2 == 0) ? s.a0 : (sel2 == 1) ? s.a1 : (sel2 == 2) ? s.a2 : s.a3;
            x2 = __shfl_sync(0xffffffffu, x2, sl2);
            float X2 = (float)__shfl_sync(0xffffffffu, s.X, sl2);
            float l1 = lg2f(x1) + X1;
            float l2 = lg2f(x2) + X2;
            float m  = fmaxf(l1, l2);
            float dd = fminf(l1, l2) - m;
            float lt = m + lg2f(1.0f + ex2f(dd));
            float loss = -LN2 * lt;
            if (!(loss <= 1e29f) || !(loss >= -1e29f)) loss = 0.0f;  // ±Inf/NaN -> 0
            if (lane == 0) g_loss_n[n] = loss / (float)tl;
        }
    }

    // fused mean-reduction: last CTA to finish does it
    __syncthreads();
    if (tid == 0) {
        __threadfence();
        int old = atomicAdd(&g_count, 1);
        s_last = (old == (int)gridDim.x - 1) ? 1 : 0;
    }
    __syncthreads();
    if (s_last) {
        __threadfence();
        float v = 0.0f;
        for (int i = tid; i < NN; i += NTHREADS) v += __ldcg(&g_loss_n[i]);
        #pragma unroll
        for (int o = 16; o; o >>= 1) v += __shfl_down_sync(0xffffffffu, v, o);
        if (lane == 0) red[wid] = v;
        __syncthreads();
        if (tid == 0) {
            float m = 0.0f;
            #pragma unroll
            for (int w = 0; w < NWARPS; w++) m += red[w];
            m /= (float)NN;
            if (isnan(m) || isinf(m)) m = 0.0f;
            out[0] = m;
            g_count = 0;   // reset for next graph replay
        }
    }
}

extern "C" void kernel_launch(void* const* d_in, const int* in_sizes, int n_in,
                              void* d_out, int out_size)
{
    const float* logits     = (const float*)d_in[0];
    const int*   labels     = (const int*)  d_in[1];
    const int*   pred_sizes = (const int*)  d_in[2];
    const int*   tgt_sizes  = (const int*)  d_in[3];
    float*       out        = (float*)d_out;

    cudaFuncSetAttribute(ctc_fused, cudaFuncAttributeMaxDynamicSharedMemorySize, SMEM_BYTES);
    ctc_fused<<<GRID, NTHREADS, SMEM_BYTES>>>(logits, labels, pred_sizes, tgt_sizes, out);
}

// round 15
// speedup vs baseline: 1.0609x; 1.0609x over previous
#include <cuda_runtime.h>
#include <math.h>
#include <stdint.h>

#define TT 512
#define NN 256
#define CC 256
#define SS 48
#define LL 97
#define LOG2E 1.4426950408889634f
#define LN2   0.6931471805599453f

#define CHUNK 16                    // timesteps per ring buffer
#define NBUF 4
#define NCHUNK (TT / CHUNK)         // 32
#define GRID NN                     // one batch row per CTA (256)
#define SLOTS 64                    // floats per timestep tile
#define GW 4                        // gather warps (wid 0..3), 4 timesteps/chunk each
#define CW 1                        // compute warp (wid 4) - hi-wid priority
#define NWARPS (GW + CW)
#define NTHREADS (NWARPS * 32)      // 160
#define BUF_F (CHUNK * SLOTS)       // 1024 floats per ring buffer
#define RING_F (NBUF * BUF_F)       // 4096 floats = 16 KB
#define NPAR 3                      // scratch triple-buffer (prefetch distance 2)
#define WSCR_F 1024                 // per-warp scratch floats per parity (4 t x 256)
#define SCRATCH_F (NPAR * GW * WSCR_F)  // 12288 floats = 48 KB
#define SMEM_BYTES ((RING_F + SCRATCH_F) * 4)   // 65536

__device__ float g_loss_n[NN];
__device__ int   g_count;           // zero-init; self-resetting per launch

__device__ __forceinline__ uint32_t s2u(const void* p) {
    return (uint32_t)__cvta_generic_to_shared(p);
}
__device__ __forceinline__ float ex2f(float x) {
    float y; asm("ex2.approx.ftz.f32 %0, %1;" : "=f"(y) : "f"(x)); return y;
}
__device__ __forceinline__ float lg2f(float x) {
    float y; asm("lg2.approx.ftz.f32 %0, %1;" : "=f"(y) : "f"(x)); return y;
}
__device__ __forceinline__ void mbar_wait(uint32_t addr, uint32_t parity) {
    asm volatile(
        "{\n"
        ".reg .pred P;\n"
        "WL%=:\n"
        "mbarrier.try_wait.parity.acquire.cta.shared::cta.b64 P, [%0], %1, 0x989680;\n"
        "@P bra WD%=;\n"
        "bra WL%=;\n"
        "WD%=:\n"
        "}\n" :: "r"(addr), "r"(parity) : "memory");
}

#define CP16(dst_u32, src_ptr) \
    asm volatile("cp.async.cg.shared.global [%0], [%1], 16;" :: "r"(dst_u32), "l"(src_ptr) : "memory")
#define CP_COMMIT() asm volatile("cp.async.commit_group;" ::: "memory")
#define CP_WAIT2()  asm volatile("cp.async.wait_group 2;" ::: "memory")
#define CP_WAIT1()  asm volatile("cp.async.wait_group 1;" ::: "memory")
#define CP_WAIT0()  asm volatile("cp.async.wait_group 0;" ::: "memory")

struct AState { float a0, a1, a2, a3, xs; int X; };

__device__ __forceinline__ void alpha_step(AState& s, float pb, float pa, float pc,
                                           float sk1f, float sk3f)
{
    float p3 = __shfl_up_sync(0xffffffffu, s.a3, 1);
    float q3 = p3 * s.xs;                  // neighbor a3 rescaled (0 on lane 0)
    float t01 = s.a0 + s.a1;
    float t23 = s.a2 + s.a3;
    float n0v = (s.a0 + q3) * pb;
    float n1v = fmaf(sk1f, q3, t01) * pa;
    float n2v = (s.a1 + s.a2) * pb;
    float n3v = fmaf(sk3f, s.a1, t23) * pc;
    s.a0 = n0v; s.a1 = n1v; s.a2 = n2v; s.a3 = n3v;
}

// PROVEN two-shfl renorm with empty-lane frame adoption. The adoption is
// LOAD-BEARING: rows with repeated labels advance the wavefront slower than
// 2 states/step, so lanes can stay empty arbitrarily long (round-13 lesson).
__device__ __forceinline__ void renorm(AState& s, int lane)
{
    float mx = fmaxf(fmaxf(s.a0, s.a1), fmaxf(s.a2, s.a3));
    int Xp = __shfl_up_sync(0xffffffffu, s.X, 1);      // neighbor X (pre-update)
    int e  = (int)(__float_as_uint(mx) >> 23);
    int eu = (e > 0) ? e : 127;
    int Xn = s.X + (eu - 127);
    Xn = (mx == 0.0f && lane > 0) ? Xp : Xn;           // empty lanes adopt neighbor frame
    float scale = __uint_as_float((unsigned)(254 - eu) << 23);
    s.a0 *= scale; s.a1 *= scale; s.a2 *= scale; s.a3 *= scale;
    s.X = Xn;
    int Xp2 = __shfl_up_sync(0xffffffffu, s.X, 1);     // neighbor FINAL X
    int d = min(126, max(-126, Xp2 - s.X));
    float x = __uint_as_float((unsigned)(d + 127) << 23);
    s.xs = (lane == 0) ? 0.0f : x;
}

__global__ __launch_bounds__(NTHREADS, 2)
void ctc_fused(const float* __restrict__ logits,
               const int*   __restrict__ labels,
               const int*   __restrict__ pred_sizes,
               const int*   __restrict__ tgt_sizes,
               float*       __restrict__ out)
{
    extern __shared__ __align__(128) float smem[];
    float* ring    = smem;                 // RING_F floats
    float* scratch = smem + RING_F;        // SCRATCH_F floats (NPAR x GW x 1024)
    __shared__ __align__(8) unsigned long long mb_full[NBUF];
    __shared__ __align__(8) unsigned long long mb_empty[NBUF];
    __shared__ float red[NWARPS];
    __shared__ int s_last;

    const int tid  = threadIdx.x;
    const int wid  = tid >> 5;
    const int lane = tid & 31;
    const int n    = blockIdx.x;           // one batch row per CTA

    if (tid == 0) {
        #pragma unroll
        for (int b = 0; b < NBUF; b++) {
            asm volatile("mbarrier.init.shared.b64 [%0], %1;" :: "r"(s2u(&mb_full[b])),  "r"(GW));
            asm volatile("mbarrier.init.shared.b64 [%0], %1;" :: "r"(s2u(&mb_empty[b])), "r"(CW));
        }
    }
    __syncthreads();

    if (wid < GW) {
        // ===== gather warps: cp.async triple-buffered, prefetch distance 2 =====
        // warp w owns timesteps c*CHUNK + w + 4r (r = 0..3), each a 1 KB row.
        const uint32_t scr_u32 = s2u(scratch) + (uint32_t)wid * (WSCR_F * 4);
        float* scr_gen = scratch + wid * WSCR_F;

        int ch0 = 0, ch1 = 0;
        if (lane < 24) {
            int2 l0 = *(const int2*)(labels + n * SS + 2 * lane);
            ch0 = l0.x; ch1 = l0.y;
        }

        #define GISSUE(k) do {                                                              \
            const uint32_t dst = scr_u32 + (uint32_t)(((k) % NPAR) * (GW * WSCR_F * 4));    \
            _Pragma("unroll")                                                               \
            for (int r = 0; r < 4; r++) {                                                   \
                const float* sp = logits + ((size_t)((k) * CHUNK + wid + 4 * r) * NN + n) * CC; \
                _Pragma("unroll")                                                           \
                for (int i = 0; i < 2; i++)                                                 \
                    CP16(dst + (uint32_t)(r * 1024) + (lane + 32 * i) * 16u,                \
                         sp + (lane + 32 * i) * 4);                                         \
            }                                                                               \
            CP_COMMIT();                                                                    \
        } while (0)

        GISSUE(0);
        GISSUE(1);

        #pragma unroll 1
        for (int c = 0; c < NCHUNK; c++) {
            const int b = c % NBUF;
            if (c + 2 < NCHUNK) { GISSUE(c + 2); CP_WAIT2(); }
            else if (c + 1 < NCHUNK) { CP_WAIT1(); }
            else { CP_WAIT0(); }
            __syncwarp();

            if (c >= NBUF) mbar_wait(s2u(&mb_empty[b]), ((c / NBUF) - 1) & 1);

            // gather 49 channels -> linear probs -> ring
            const float* buf = scr_gen + (c % NPAR) * (GW * WSCR_F);
            if (lane <= 24) {
                #pragma unroll
                for (int r = 0; r < 4; r++) {
                    const float* base = buf + r * 256;
                    const int j = wid + 4 * r;
                    float p0 = ex2f(base[ch0] * LOG2E);   // lane 24: ch0=0 = blank -> slot 48
                    float p1 = ex2f(base[ch1] * LOG2E);
                    float* tp = ring + (size_t)(b * CHUNK + j) * SLOTS;
                    *(float2*)(tp + 2 * lane) = make_float2(p0, p1);
                }
            }
            __syncwarp();
            if (lane == 0)
                asm volatile("mbarrier.arrive.shared.b64 _, [%0];" :: "r"(s2u(&mb_full[b])) : "memory");
        }
        #undef GISSUE
    } else {
        // ================= compute warp (this CTA's batch row) =================
        int lab_a = (2 * lane     < SS) ? labels[n * SS + 2 * lane]     : 0;
        int lab_b = (2 * lane + 1 < SS) ? labels[n * SS + 2 * lane + 1] : 0;
        int lab_p = (2 * lane - 1 >= 0) ? labels[n * SS + 2 * lane - 1] : 0;
        const float sk1f = ((lab_a != 0) && (lab_a != lab_p)) ? 1.0f : 0.0f;
        const float sk3f = ((lab_b != 0) && (lab_b != lab_a)) ? 1.0f : 0.0f;
        const int in_len = pred_sizes[n];
        const int pair_off = (lane < 24) ? 2 * lane : 48;

        AState s;
        s.a0 = 0.0f; s.a1 = 0.0f; s.a2 = 0.0f; s.a3 = 0.0f;
        s.X = 0;
        s.xs = (lane == 0) ? 0.0f : 1.0f;

        #pragma unroll 1
        for (int c = 0; c < NCHUNK; c++) {
            const int b = c % NBUF;
            mbar_wait(s2u(&mb_full[b]), (c / NBUF) & 1);
            const float* base = ring + (size_t)(b * CHUNK) * SLOTS;
            const bool fast = (c > 0) && ((c + 1) * CHUNK <= in_len);

            if (fast) {
                // batch-load the entire chunk to registers, then free the ring slot early
                float pa[CHUNK], pc[CHUNK], pb[CHUNK];
                #pragma unroll
                for (int j = 0; j < CHUNK; j++) {
                    const float* rp = base + j * SLOTS;
                    float2 f2 = *(const float2*)(rp + pair_off);
                    pa[j] = f2.x; pc[j] = f2.y;
                    pb[j] = rp[48];
                }
                __syncwarp();
                if (lane == 0)
                    asm volatile("mbarrier.arrive.shared.b64 _, [%0];" :: "r"(s2u(&mb_empty[b])) : "memory");

                #pragma unroll
                for (int j = 0; j < CHUNK; j++) {
                    alpha_step(s, pb[j], pa[j], pc[j], sk1f, sk3f);
                    if ((j & 3) == 3) renorm(s, lane);
                }
            } else {
                #pragma unroll 1
                for (int j = 0; j < CHUNK; j++) {
                    const int t = c * CHUNK + j;
                    const float* rp = base + j * SLOTS;
                    if (t < in_len) {
                        float2 f2 = *(const float2*)(rp + pair_off);
                        float pbv = rp[48];
                        if (t == 0) {
                            if (lane == 0) { s.a0 = pbv; s.a1 = f2.x; }
                        } else {
                            alpha_step(s, pbv, f2.x, f2.y, sk1f, sk3f);
                        }
                        if ((t & 3) == 3) renorm(s, lane);
                    }
                }
                if (lane == 0)
                    asm volatile("mbarrier.arrive.shared.b64 _, [%0];" :: "r"(s2u(&mb_empty[b])) : "memory");
            }
        }

        // per-row loss: true log2(alpha_l) = lg2(stored) + X_lane
        {
            int tl = tgt_sizes[n];
            int i1 = 2 * tl - 1, i2 = 2 * tl;
            int sel1 = i1 & 3, sl1 = i1 >> 2;
            float x1 = (sel1 == 0) ? s.a0 : (sel1 == 1) ? s.a1 : (sel1 == 2) ? s.a2 : s.a3;
            x1 = __shfl_sync(0xffffffffu, x1, sl1);
            float X1 = (float)__shfl_sync(0xffffffffu, s.X, sl1);
            int sel2 = i2 & 3, sl2 = i2 >> 2;
            float x2 = (sel2 == 0) ? s.a0 : (sel2 == 1) ? s.a1 : (sel2 == 2) ? s.a2 : s.a3;
            x2 = __shfl_sync(0xffffffffu, x2, sl2);
            float X2 = (float)__shfl_sync(0xffffffffu, s.X, sl2);
            float l1 = lg2f(x1) + X1;
            float l2 = lg2f(x2) + X2;
            float m  = fmaxf(l1, l2);
            float dd = fminf(l1, l2) - m;
            float lt = m + lg2f(1.0f + ex2f(dd));
            float loss = -LN2 * lt;
            if (!(loss <= 1e29f) || !(loss >= -1e29f)) loss = 0.0f;  // ±Inf/NaN -> 0
            if (lane == 0) g_loss_n[n] = loss / (float)tl;
        }
    }

    // fused mean-reduction: last CTA to finish does it
    __syncthreads();
    if (tid == 0) {
        __threadfence();
        int old = atomicAdd(&g_count, 1);
        s_last = (old == (int)gridDim.x - 1) ? 1 : 0;
    }
    __syncthreads();
    if (s_last) {
        __threadfence();
        float v = 0.0f;
        for (int i = tid; i < NN; i += NTHREADS) v += __ldcg(&g_loss_n[i]);
        #pragma unroll
        for (int o = 16; o; o >>= 1) v += __shfl_down_sync(0xffffffffu, v, o);
        if (lane == 0) red[wid] = v;
        __syncthreads();
        if (tid == 0) {
            float m = 0.0f;
            #pragma unroll
            for (int w = 0; w < NWARPS; w++) m += red[w];
            m /= (float)NN;
            if (isnan(m) || isinf(m)) m = 0.0f;
            out[0] = m;
            g_count = 0;   // reset for next graph replay
        }
    }
}

extern "C" void kernel_launch(void* const* d_in, const int* in_sizes, int n_in,
                              void* d_out, int out_size)
{
    const float* logits     = (const float*)d_in[0];
    const int*   labels     = (const int*)  d_in[1];
    const int*   pred_sizes = (const int*)  d_in[2];
    const int*   tgt_sizes  = (const int*)  d_in[3];
    float*       out        = (float*)d_out;

    cudaFuncSetAttribute(ctc_fused, cudaFuncAttributeMaxDynamicSharedMemorySize, SMEM_BYTES);
    ctc_fused<<<GRID, NTHREADS, SMEM_BYTES>>>(logits, labels, pred_sizes, tgt_sizes, out);
}